// round 1
// baseline (speedup 1.0000x reference)
#include <cuda_runtime.h>
#include <cuda_bf16.h>

#define NMAX 50000
#define EMAX 600000
#define DIM 128
#define HEADS 4
#define FH 32
#define NEG_SLOPE 0.2f

// ---------------- scratch (static device globals; no allocs) ----------------
__device__ float d_x[NMAX * DIM];       // current node features
__device__ float d_h[NMAX * DIM];       // h = x @ W
__device__ float d_agg[NMAX * DIM];     // aggregated messages
__device__ float d_asrc[NMAX * HEADS];  // alpha_src per node
__device__ float d_adst[NMAX * HEADS];  // alpha_dst per node
__device__ float d_alpha[EMAX * HEADS]; // per-CSR-slot exp values
__device__ float d_gate[NMAX];          // exp(sigmoid(gate)) per node
__device__ float d_gvec[2 * DIM];       // unnormalized pooled vectors
__device__ float d_gsum[2];             // softmax denominators
__device__ int d_deg[NMAX];
__device__ int d_off[NMAX + 1];
__device__ int d_cur[NMAX];
__device__ int d_csrc[EMAX];            // src node per sorted incoming edge

__device__ __forceinline__ float leaky(float x) { return x > 0.f ? x : NEG_SLOPE * x; }

// ---------------- embed gather ----------------
__global__ void k_gather(const int* __restrict__ ids, const float* __restrict__ embed, int n) {
    int t = blockIdx.x * blockDim.x + threadIdx.x;   // one float4 per thread
    if (t >= n * 32) return;
    int node = t >> 5, j = t & 31;
    ((float4*)(d_x + node * DIM))[j] = ((const float4*)(embed + (size_t)ids[node] * DIM))[j];
}

// ---------------- CSR build ----------------
__global__ void k_zero_deg(int n) {
    int i = blockIdx.x * blockDim.x + threadIdx.x;
    if (i < n) d_deg[i] = 0;
}

__global__ void k_hist(const int* __restrict__ dst, int E) {
    int i = blockIdx.x * blockDim.x + threadIdx.x;
    if (i < E) atomicAdd(&d_deg[dst[i]], 1);
}

__global__ void k_scan(int n) {
    __shared__ int wsum[32];
    __shared__ int s_carry;
    int tid = threadIdx.x, lane = tid & 31, wid = tid >> 5;
    if (tid == 0) s_carry = 0;
    __syncthreads();
    for (int base = 0; base < n; base += blockDim.x) {
        int i = base + tid;
        int v = (i < n) ? d_deg[i] : 0;
        int x = v;
        #pragma unroll
        for (int d = 1; d < 32; d <<= 1) {
            int y = __shfl_up_sync(0xFFFFFFFFu, x, d);
            if (lane >= d) x += y;
        }
        if (lane == 31) wsum[wid] = x;
        __syncthreads();
        if (wid == 0) {
            int w = wsum[lane];
            #pragma unroll
            for (int d = 1; d < 32; d <<= 1) {
                int y = __shfl_up_sync(0xFFFFFFFFu, w, d);
                if (lane >= d) w += y;
            }
            wsum[lane] = w;
        }
        __syncthreads();
        int incl = x + (wid ? wsum[wid - 1] : 0);
        int total = wsum[31];
        int carry = s_carry;
        if (i < n) {
            int ex = carry + incl - v;
            d_off[i] = ex;
            d_cur[i] = ex;
        }
        __syncthreads();
        if (tid == 0) s_carry = carry + total;
        __syncthreads();
    }
    if (tid == 0) d_off[n] = s_carry;
}

__global__ void k_scatter(const int* __restrict__ src, const int* __restrict__ dst, int E) {
    int i = blockIdx.x * blockDim.x + threadIdx.x;
    if (i < E) {
        int p = atomicAdd(&d_cur[dst[i]], 1);
        d_csrc[p] = src[i];
    }
}

// ---------------- GEMM: h = x @ W, plus per-node attention dots ----------------
__global__ void k_gemm(const float* __restrict__ W,
                       const float* __restrict__ att_s,
                       const float* __restrict__ att_d, int n) {
    __shared__ float4 xs[8][32];
    int j = threadIdx.x;        // output column 0..127
    int n0 = blockIdx.x * 8;
    for (int t = j; t < 8 * 32; t += 128) {
        int i = t >> 5, k4 = t & 31;
        int node = n0 + i;
        xs[i][k4] = (node < n) ? ((const float4*)(d_x + (size_t)node * DIM))[k4]
                               : make_float4(0.f, 0.f, 0.f, 0.f);
    }
    __syncthreads();

    float acc[8] = {0.f, 0.f, 0.f, 0.f, 0.f, 0.f, 0.f, 0.f};
    #pragma unroll 8
    for (int k4 = 0; k4 < 32; k4++) {
        float w0 = W[(4 * k4 + 0) * DIM + j];
        float w1 = W[(4 * k4 + 1) * DIM + j];
        float w2 = W[(4 * k4 + 2) * DIM + j];
        float w3 = W[(4 * k4 + 3) * DIM + j];
        #pragma unroll
        for (int i = 0; i < 8; i++) {
            float4 xv = xs[i][k4];
            acc[i] += xv.x * w0 + xv.y * w1 + xv.z * w2 + xv.w * w3;
        }
    }

    int h = j >> 5, f = j & 31;
    float cs = att_s[h * FH + f];
    float cd = att_d[h * FH + f];
    #pragma unroll
    for (int i = 0; i < 8; i++) {
        int node = n0 + i;
        if (node >= n) break;
        d_h[(size_t)node * DIM + j] = acc[i];
        float vs = acc[i] * cs;
        float vd = acc[i] * cd;
        #pragma unroll
        for (int d = 16; d; d >>= 1) {
            vs += __shfl_down_sync(0xFFFFFFFFu, vs, d);
            vd += __shfl_down_sync(0xFFFFFFFFu, vd, d);
        }
        if (f == 0) {
            d_asrc[node * HEADS + h] = vs;
            d_adst[node * HEADS + h] = vd;
        }
    }
}

// ---------------- fused per-node attention (warp per node, no atomics) -------
__global__ void k_attn(int n) {
    int warp = (blockIdx.x * blockDim.x + threadIdx.x) >> 5;
    int lane = threadIdx.x & 31;
    if (warp >= n) return;
    int nidx = warp;
    int beg = d_off[nidx], end = d_off[nidx + 1];

    float4 ad4 = ((const float4*)d_adst)[nidx];
    float ad[4] = {ad4.x, ad4.y, ad4.z, ad4.w};
    float4 as4 = ((const float4*)d_asrc)[nidx];
    float es[4];
    es[0] = leaky(as4.x + ad[0]);
    es[1] = leaky(as4.y + ad[1]);
    es[2] = leaky(as4.z + ad[2]);
    es[3] = leaky(as4.w + ad[3]);

    float m[4] = {es[0], es[1], es[2], es[3]};
    for (int p = beg + lane; p < end; p += 32) {
        int s = d_csrc[p];
        float4 a = ((const float4*)d_asrc)[s];
        m[0] = fmaxf(m[0], leaky(a.x + ad[0]));
        m[1] = fmaxf(m[1], leaky(a.y + ad[1]));
        m[2] = fmaxf(m[2], leaky(a.z + ad[2]));
        m[3] = fmaxf(m[3], leaky(a.w + ad[3]));
    }
    #pragma unroll
    for (int d = 16; d; d >>= 1) {
        #pragma unroll
        for (int h = 0; h < 4; h++)
            m[h] = fmaxf(m[h], __shfl_xor_sync(0xFFFFFFFFu, m[h], d));
    }

    float sum[4] = {0.f, 0.f, 0.f, 0.f};
    for (int p = beg + lane; p < end; p += 32) {
        int s = d_csrc[p];
        float4 a = ((const float4*)d_asrc)[s];
        float e0 = __expf(leaky(a.x + ad[0]) - m[0]);
        float e1 = __expf(leaky(a.y + ad[1]) - m[1]);
        float e2 = __expf(leaky(a.z + ad[2]) - m[2]);
        float e3 = __expf(leaky(a.w + ad[3]) - m[3]);
        ((float4*)d_alpha)[p] = make_float4(e0, e1, e2, e3);
        sum[0] += e0; sum[1] += e1; sum[2] += e2; sum[3] += e3;
    }
    #pragma unroll
    for (int d = 16; d; d >>= 1) {
        #pragma unroll
        for (int h = 0; h < 4; h++)
            sum[h] += __shfl_xor_sync(0xFFFFFFFFu, sum[h], d);
    }

    float exself[4], inv[4];
    #pragma unroll
    for (int h = 0; h < 4; h++) {
        exself[h] = __expf(es[h] - m[h]);
        inv[h] = 1.f / (sum[h] + exself[h] + 1e-16f);
    }

    // pass 3: feature-parallel accumulation (lane covers dims [4*lane, 4*lane+4))
    int h3 = lane >> 3;
    float a_self = exself[h3] * inv[h3];
    float4 hv = ((const float4*)(d_h + (size_t)nidx * DIM))[lane];
    float4 acc;
    acc.x = a_self * hv.x; acc.y = a_self * hv.y;
    acc.z = a_self * hv.z; acc.w = a_self * hv.w;
    for (int p = beg; p < end; p++) {
        int s = d_csrc[p];
        float a = d_alpha[p * 4 + h3] * inv[h3];
        float4 v = ((const float4*)(d_h + (size_t)s * DIM))[lane];
        acc.x += a * v.x; acc.y += a * v.y;
        acc.z += a * v.z; acc.w += a * v.w;
    }
    ((float4*)(d_agg + (size_t)nidx * DIM))[lane] = acc;
}

// ---------------- x = relu(agg + bias) ----------------
__global__ void k_relu_bias(const float* __restrict__ bias, int n) {
    int t = blockIdx.x * blockDim.x + threadIdx.x;
    if (t >= n * 32) return;
    int j4 = t & 31;
    float4 b = ((const float4*)bias)[j4];
    float4 v = ((const float4*)d_agg)[t];
    v.x = fmaxf(v.x + b.x, 0.f);
    v.y = fmaxf(v.y + b.y, 0.f);
    v.z = fmaxf(v.z + b.z, 0.f);
    v.w = fmaxf(v.w + b.w, 0.f);
    ((float4*)d_x)[t] = v;
}

// ---------------- global attention pooling ----------------
__global__ void k_zero_gate(int g) {
    int j = threadIdx.x;
    d_gvec[g * DIM + j] = 0.f;
    if (j == 0) d_gsum[g] = 0.f;
}

__global__ void k_gate(const float* __restrict__ gw, const float* __restrict__ gb,
                       int g, int n) {
    __shared__ float part[8];
    int warp = (blockIdx.x * blockDim.x + threadIdx.x) >> 5;
    int lane = threadIdx.x & 31;
    float eg = 0.f;
    if (warp < n) {
        float4 xv = ((const float4*)(d_x + (size_t)warp * DIM))[lane];
        float4 wv = ((const float4*)gw)[lane];
        float t = xv.x * wv.x + xv.y * wv.y + xv.z * wv.z + xv.w * wv.w;
        #pragma unroll
        for (int d = 16; d; d >>= 1) t += __shfl_down_sync(0xFFFFFFFFu, t, d);
        if (lane == 0) {
            float s = 1.f / (1.f + __expf(-(t + gb[0])));
            eg = __expf(s);
            d_gate[warp] = eg;
        }
    }
    if (lane == 0) part[threadIdx.x >> 5] = eg;
    __syncthreads();
    if (threadIdx.x == 0) {
        float s = 0.f;
        #pragma unroll
        for (int i = 0; i < 8; i++) s += part[i];
        atomicAdd(&d_gsum[g], s);
    }
}

__global__ void k_gsum(int g, int n) {
    int j = threadIdx.x;   // 0..127
    float acc = 0.f;
    for (int i = blockIdx.x; i < n; i += gridDim.x)
        acc += d_gate[i] * d_x[(size_t)i * DIM + j];
    atomicAdd(&d_gvec[g * DIM + j], acc);
}

// ---------------- final MLP ----------------
__global__ void k_final(const float* __restrict__ fc1_w, const float* __restrict__ fc1_b,
                        const float* __restrict__ fc2_w, const float* __restrict__ fc2_b,
                        float* __restrict__ out) {
    __shared__ float red[4];
    int j = threadIdx.x;   // 0..127
    float inv1 = 1.f / d_gsum[0];
    float inv2 = 1.f / d_gsum[1];
    float acc = fc1_b[j];
    #pragma unroll 4
    for (int k = 0; k < DIM; k++)
        acc += d_gvec[k] * inv1 * fc1_w[k * DIM + j];
    #pragma unroll 4
    for (int k = 0; k < DIM; k++)
        acc += d_gvec[DIM + k] * inv2 * fc1_w[(DIM + k) * DIM + j];
    float v = fmaxf(acc, 0.f) * fc2_w[j];
    #pragma unroll
    for (int d = 16; d; d >>= 1) v += __shfl_down_sync(0xFFFFFFFFu, v, d);
    if ((j & 31) == 0) red[j >> 5] = v;
    __syncthreads();
    if (j == 0) out[0] = red[0] + red[1] + red[2] + red[3] + fc2_b[0];
}

// ---------------- orchestration ----------------
extern "C" void kernel_launch(void* const* d_in, const int* in_sizes, int n_in,
                              void* d_out, int out_size) {
    (void)n_in; (void)out_size;
    const int*   x1    = (const int*)d_in[0];
    const int*   x2    = (const int*)d_in[1];
    const int*   ei1   = (const int*)d_in[2];
    const int*   ei2   = (const int*)d_in[3];
    const float* embed = (const float*)d_in[4];
    const float* W     = (const float*)d_in[5];
    const float* att_s = (const float*)d_in[6];
    const float* att_d = (const float*)d_in[7];
    const float* bias  = (const float*)d_in[8];
    const float* gw    = (const float*)d_in[9];
    const float* gb    = (const float*)d_in[10];
    const float* fc1w  = (const float*)d_in[11];
    const float* fc1b  = (const float*)d_in[12];
    const float* fc2w  = (const float*)d_in[13];
    const float* fc2b  = (const float*)d_in[14];

    int N = in_sizes[0];
    int E = in_sizes[2] / 2;

    for (int g = 0; g < 2; g++) {
        const int* ids = g ? x2 : x1;
        const int* ei  = g ? ei2 : ei1;

        k_gather<<<(N * 32 + 127) / 128, 128>>>(ids, embed, N);
        k_zero_deg<<<(N + 255) / 256, 256>>>(N);
        k_hist<<<(E + 255) / 256, 256>>>(ei + E, E);
        k_scan<<<1, 1024>>>(N);
        k_scatter<<<(E + 255) / 256, 256>>>(ei, ei + E, E);

        for (int l = 0; l < 3; l++) {
            k_gemm<<<(N + 7) / 8, 128>>>(W + l * DIM * DIM,
                                         att_s + l * HEADS * FH,
                                         att_d + l * HEADS * FH, N);
            k_attn<<<(N * 32 + 255) / 256, 256>>>(N);
            k_relu_bias<<<(N * 32 + 255) / 256, 256>>>(bias + l * DIM, N);
        }

        k_zero_gate<<<1, 128>>>(g);
        k_gate<<<(N + 7) / 8, 256>>>(gw, gb, g, N);
        k_gsum<<<512, 128>>>(g, N);
    }
    k_final<<<1, 128>>>(fc1w, fc1b, fc2w, fc2b, (float*)d_out);
}

// round 2
// speedup vs baseline: 1.2462x; 1.2462x over previous
#include <cuda_runtime.h>
#include <cuda_bf16.h>

#define NMAX 50000
#define EMAX 600000
#define NT2 (2 * NMAX)
#define ET2 (2 * EMAX)
#define DIM 128
#define HEADS 4
#define FH 32
#define NEG_SLOPE 0.2f

// ---------------- scratch (static device globals; no allocs) ----------------
__device__ float d_x[NT2 * DIM];        // current node features (both graphs)
__device__ float d_h[NT2 * DIM];        // h = x @ W
__device__ float d_asrc[NT2 * HEADS];
__device__ float d_adst[NT2 * HEADS];
__device__ float d_alpha[ET2 * HEADS];  // per-CSR-slot exp values
__device__ float d_gate[NT2];
__device__ float d_gvec[2 * DIM];
__device__ float d_gsum[2];
__device__ int d_deg[NT2];
__device__ int d_off[NT2 + 1];
__device__ int d_cur[NT2];
__device__ int d_csrc[ET2];
__device__ int d_bsum[128];
__device__ int d_boff[128];

__device__ __forceinline__ float leaky(float x) { return x > 0.f ? x : NEG_SLOPE * x; }

// ---------------- embed gather (both graphs) ----------------
__global__ void k_gather(const int* __restrict__ x1, const int* __restrict__ x2,
                         const float* __restrict__ embed, int n) {
    int t = blockIdx.x * blockDim.x + threadIdx.x;
    if (t >= 2 * n * 32) return;
    int node = t >> 5, j = t & 31;
    int id = (node < n) ? x1[node] : x2[node - n];
    ((float4*)(d_x + (size_t)node * DIM))[j] = ((const float4*)(embed + (size_t)id * DIM))[j];
}

// ---------------- CSR build ----------------
__global__ void k_zero_deg(int nt) {
    int i = blockIdx.x * blockDim.x + threadIdx.x;
    if (i < nt) d_deg[i] = 0;
}

__global__ void k_hist(const int* __restrict__ dst, int E, int off) {
    int i = blockIdx.x * blockDim.x + threadIdx.x;
    if (i < E) atomicAdd(&d_deg[dst[i] + off], 1);
}

// --- hierarchical exclusive scan over d_deg[0..nt) -> d_off, d_cur ---
// 2048 elements per block (256 threads x 8)
__global__ void k_blocksum(int nt) {
    __shared__ int ws[8];
    int base = blockIdx.x * 2048 + threadIdx.x * 8;
    int s = 0;
    #pragma unroll
    for (int k = 0; k < 8; k++) {
        int i = base + k;
        if (i < nt) s += d_deg[i];
    }
    #pragma unroll
    for (int d = 16; d; d >>= 1) s += __shfl_down_sync(0xFFFFFFFFu, s, d);
    if ((threadIdx.x & 31) == 0) ws[threadIdx.x >> 5] = s;
    __syncthreads();
    if (threadIdx.x == 0) {
        int t = 0;
        #pragma unroll
        for (int w = 0; w < 8; w++) t += ws[w];
        d_bsum[blockIdx.x] = t;
    }
}

__global__ void k_scanb(int nb) {   // one block, 128 threads, nb <= 128
    __shared__ int ws[4];
    int tid = threadIdx.x, lane = tid & 31, wid = tid >> 5;
    int v = (tid < nb) ? d_bsum[tid] : 0;
    int x = v;
    #pragma unroll
    for (int d = 1; d < 32; d <<= 1) {
        int y = __shfl_up_sync(0xFFFFFFFFu, x, d);
        if (lane >= d) x += y;
    }
    if (lane == 31) ws[wid] = x;
    __syncthreads();
    int add = 0;
    for (int w = 0; w < wid; w++) add += ws[w];
    if (tid < nb) d_boff[tid] = add + x - v;   // exclusive
}

__global__ void k_scanlocal(int nt) {
    __shared__ int wtot[8];
    __shared__ int wexc[8];
    int tid = threadIdx.x, lane = tid & 31, wid = tid >> 5;
    int base = blockIdx.x * 2048 + tid * 8;
    int vals[8];
    int tsum = 0;
    #pragma unroll
    for (int k = 0; k < 8; k++) {
        int i = base + k;
        vals[k] = (i < nt) ? d_deg[i] : 0;
        tsum += vals[k];
    }
    int x = tsum;
    #pragma unroll
    for (int d = 1; d < 32; d <<= 1) {
        int y = __shfl_up_sync(0xFFFFFFFFu, x, d);
        if (lane >= d) x += y;
    }
    if (lane == 31) wtot[wid] = x;
    __syncthreads();
    if (tid == 0) {
        int acc = 0;
        #pragma unroll
        for (int w = 0; w < 8; w++) { wexc[w] = acc; acc += wtot[w]; }
    }
    __syncthreads();
    int running = d_boff[blockIdx.x] + wexc[wid] + (x - tsum);
    #pragma unroll
    for (int k = 0; k < 8; k++) {
        int i = base + k;
        if (i < nt) {
            d_off[i] = running;
            d_cur[i] = running;
            running += vals[k];
            if (i == nt - 1) d_off[nt] = running;
        }
    }
}

__global__ void k_scatter(const int* __restrict__ src, const int* __restrict__ dst,
                          int E, int off) {
    int i = blockIdx.x * blockDim.x + threadIdx.x;
    if (i < E) {
        int p = atomicAdd(&d_cur[dst[i] + off], 1);
        d_csrc[p] = src[i] + off;
    }
}

// ---------------- GEMM: h = x @ W, plus per-node attention dots ----------------
// 16 rows per block, 128 threads (thread = output column)
__global__ void k_gemm(const float* __restrict__ W,
                       const float* __restrict__ att_s,
                       const float* __restrict__ att_d, int nt) {
    __shared__ float4 xs[16][32];
    int j = threadIdx.x;
    int n0 = blockIdx.x * 16;
    #pragma unroll
    for (int t = j; t < 16 * 32; t += 128) {
        int i = t >> 5, k4 = t & 31;
        int node = n0 + i;
        xs[i][k4] = (node < nt) ? ((const float4*)(d_x + (size_t)node * DIM))[k4]
                                : make_float4(0.f, 0.f, 0.f, 0.f);
    }
    __syncthreads();

    float acc[16];
    #pragma unroll
    for (int i = 0; i < 16; i++) acc[i] = 0.f;
    #pragma unroll 8
    for (int k4 = 0; k4 < 32; k4++) {
        float w0 = W[(4 * k4 + 0) * DIM + j];
        float w1 = W[(4 * k4 + 1) * DIM + j];
        float w2 = W[(4 * k4 + 2) * DIM + j];
        float w3 = W[(4 * k4 + 3) * DIM + j];
        #pragma unroll
        for (int i = 0; i < 16; i++) {
            float4 xv = xs[i][k4];
            acc[i] += xv.x * w0 + xv.y * w1 + xv.z * w2 + xv.w * w3;
        }
    }

    int h = j >> 5;           // head == warp id
    float cs = att_s[j];      // [HEADS][FH] flattened == feature index
    float cd = att_d[j];
    #pragma unroll
    for (int i = 0; i < 16; i++) {
        int node = n0 + i;
        if (node >= nt) break;
        d_h[(size_t)node * DIM + j] = acc[i];
        float vs = acc[i] * cs;
        float vd = acc[i] * cd;
        #pragma unroll
        for (int d = 16; d; d >>= 1) {
            vs += __shfl_down_sync(0xFFFFFFFFu, vs, d);
            vd += __shfl_down_sync(0xFFFFFFFFu, vd, d);
        }
        if ((j & 31) == 0) {
            d_asrc[node * HEADS + h] = vs;
            d_adst[node * HEADS + h] = vd;
        }
    }
}

// ---------------- fused per-node attention + bias + relu (warp per node) -----
__global__ void k_attn(const float* __restrict__ bias, int nt) {
    int warp = (blockIdx.x * blockDim.x + threadIdx.x) >> 5;
    int lane = threadIdx.x & 31;
    if (warp >= nt) return;
    int nidx = warp;
    int beg = d_off[nidx], end = d_off[nidx + 1];

    float4 ad4 = ((const float4*)d_adst)[nidx];
    float ad[4] = {ad4.x, ad4.y, ad4.z, ad4.w};
    float4 as4 = ((const float4*)d_asrc)[nidx];
    float es[4];
    es[0] = leaky(as4.x + ad[0]);
    es[1] = leaky(as4.y + ad[1]);
    es[2] = leaky(as4.z + ad[2]);
    es[3] = leaky(as4.w + ad[3]);

    float m[4] = {es[0], es[1], es[2], es[3]};
    for (int p = beg + lane; p < end; p += 32) {
        int s = d_csrc[p];
        float4 a = ((const float4*)d_asrc)[s];
        m[0] = fmaxf(m[0], leaky(a.x + ad[0]));
        m[1] = fmaxf(m[1], leaky(a.y + ad[1]));
        m[2] = fmaxf(m[2], leaky(a.z + ad[2]));
        m[3] = fmaxf(m[3], leaky(a.w + ad[3]));
    }
    #pragma unroll
    for (int d = 16; d; d >>= 1) {
        #pragma unroll
        for (int h = 0; h < 4; h++)
            m[h] = fmaxf(m[h], __shfl_xor_sync(0xFFFFFFFFu, m[h], d));
    }

    float sum[4] = {0.f, 0.f, 0.f, 0.f};
    for (int p = beg + lane; p < end; p += 32) {
        int s = d_csrc[p];
        float4 a = ((const float4*)d_asrc)[s];
        float e0 = __expf(leaky(a.x + ad[0]) - m[0]);
        float e1 = __expf(leaky(a.y + ad[1]) - m[1]);
        float e2 = __expf(leaky(a.z + ad[2]) - m[2]);
        float e3 = __expf(leaky(a.w + ad[3]) - m[3]);
        ((float4*)d_alpha)[p] = make_float4(e0, e1, e2, e3);
        sum[0] += e0; sum[1] += e1; sum[2] += e2; sum[3] += e3;
    }
    #pragma unroll
    for (int d = 16; d; d >>= 1) {
        #pragma unroll
        for (int h = 0; h < 4; h++)
            sum[h] += __shfl_xor_sync(0xFFFFFFFFu, sum[h], d);
    }

    float exself[4], inv[4];
    #pragma unroll
    for (int h = 0; h < 4; h++) {
        exself[h] = __expf(es[h] - m[h]);
        inv[h] = 1.f / (sum[h] + exself[h] + 1e-16f);
    }

    // pass 3: feature-parallel accumulation, fused bias + relu
    int h3 = lane >> 3;
    float a_self = exself[h3] * inv[h3];
    float4 hv = ((const float4*)(d_h + (size_t)nidx * DIM))[lane];
    float4 acc;
    acc.x = a_self * hv.x; acc.y = a_self * hv.y;
    acc.z = a_self * hv.z; acc.w = a_self * hv.w;
    for (int p = beg; p < end; p++) {
        int s = d_csrc[p];
        float a = d_alpha[p * 4 + h3] * inv[h3];
        float4 v = ((const float4*)(d_h + (size_t)s * DIM))[lane];
        acc.x += a * v.x; acc.y += a * v.y;
        acc.z += a * v.z; acc.w += a * v.w;
    }
    float4 b = ((const float4*)bias)[lane];
    acc.x = fmaxf(acc.x + b.x, 0.f);
    acc.y = fmaxf(acc.y + b.y, 0.f);
    acc.z = fmaxf(acc.z + b.z, 0.f);
    acc.w = fmaxf(acc.w + b.w, 0.f);
    ((float4*)(d_x + (size_t)nidx * DIM))[lane] = acc;
}

// ---------------- global attention pooling ----------------
__global__ void k_zero_gate() {
    int j = threadIdx.x;
    if (j < 2 * DIM) d_gvec[j] = 0.f;
    if (j < 2) d_gsum[j] = 0.f;
}

__global__ void k_gate(const float* __restrict__ gw, const float* __restrict__ gb,
                       int n) {
    __shared__ float part[2];
    int warp = (blockIdx.x * blockDim.x + threadIdx.x) >> 5;
    int lane = threadIdx.x & 31;
    if (threadIdx.x < 2) part[threadIdx.x] = 0.f;
    __syncthreads();
    if (warp < 2 * n) {
        float4 xv = ((const float4*)(d_x + (size_t)warp * DIM))[lane];
        float4 wv = ((const float4*)gw)[lane];
        float t = xv.x * wv.x + xv.y * wv.y + xv.z * wv.z + xv.w * wv.w;
        #pragma unroll
        for (int d = 16; d; d >>= 1) t += __shfl_down_sync(0xFFFFFFFFu, t, d);
        if (lane == 0) {
            float s = 1.f / (1.f + __expf(-(t + gb[0])));
            float eg = __expf(s);
            d_gate[warp] = eg;
            atomicAdd(&part[warp >= n ? 1 : 0], eg);
        }
    }
    __syncthreads();
    if (threadIdx.x < 2 && part[threadIdx.x] != 0.f)
        atomicAdd(&d_gsum[threadIdx.x], part[threadIdx.x]);
}

__global__ void k_gsum(int n) {
    int j = threadIdx.x;   // 0..127
    int g = (blockIdx.x >= 512) ? 1 : 0;
    int b = blockIdx.x & 511;
    float acc = 0.f;
    for (int i = b; i < n; i += 512) {
        int node = g * n + i;
        acc += d_gate[node] * d_x[(size_t)node * DIM + j];
    }
    atomicAdd(&d_gvec[g * DIM + j], acc);
}

// ---------------- final MLP ----------------
__global__ void k_final(const float* __restrict__ fc1_w, const float* __restrict__ fc1_b,
                        const float* __restrict__ fc2_w, const float* __restrict__ fc2_b,
                        float* __restrict__ out) {
    __shared__ float red[4];
    int j = threadIdx.x;
    float inv1 = 1.f / d_gsum[0];
    float inv2 = 1.f / d_gsum[1];
    float acc = fc1_b[j];
    #pragma unroll 4
    for (int k = 0; k < DIM; k++)
        acc += d_gvec[k] * inv1 * fc1_w[k * DIM + j];
    #pragma unroll 4
    for (int k = 0; k < DIM; k++)
        acc += d_gvec[DIM + k] * inv2 * fc1_w[(DIM + k) * DIM + j];
    float v = fmaxf(acc, 0.f) * fc2_w[j];
    #pragma unroll
    for (int d = 16; d; d >>= 1) v += __shfl_down_sync(0xFFFFFFFFu, v, d);
    if ((j & 31) == 0) red[j >> 5] = v;
    __syncthreads();
    if (j == 0) out[0] = red[0] + red[1] + red[2] + red[3] + fc2_b[0];
}

// ---------------- orchestration ----------------
extern "C" void kernel_launch(void* const* d_in, const int* in_sizes, int n_in,
                              void* d_out, int out_size) {
    (void)n_in; (void)out_size;
    const int*   x1    = (const int*)d_in[0];
    const int*   x2    = (const int*)d_in[1];
    const int*   ei1   = (const int*)d_in[2];
    const int*   ei2   = (const int*)d_in[3];
    const float* embed = (const float*)d_in[4];
    const float* W     = (const float*)d_in[5];
    const float* att_s = (const float*)d_in[6];
    const float* att_d = (const float*)d_in[7];
    const float* bias  = (const float*)d_in[8];
    const float* gw    = (const float*)d_in[9];
    const float* gb    = (const float*)d_in[10];
    const float* fc1w  = (const float*)d_in[11];
    const float* fc1b  = (const float*)d_in[12];
    const float* fc2w  = (const float*)d_in[13];
    const float* fc2b  = (const float*)d_in[14];

    int N = in_sizes[0];
    int E = in_sizes[2] / 2;
    int NT = 2 * N;
    int nb = (NT + 2047) / 2048;

    k_gather<<<(NT * 32 + 255) / 256, 256>>>(x1, x2, embed, N);
    k_zero_deg<<<(NT + 255) / 256, 256>>>(NT);
    k_hist<<<(E + 255) / 256, 256>>>(ei1 + E, E, 0);
    k_hist<<<(E + 255) / 256, 256>>>(ei2 + E, E, N);
    k_blocksum<<<nb, 256>>>(NT);
    k_scanb<<<1, 128>>>(nb);
    k_scanlocal<<<nb, 256>>>(NT);
    k_scatter<<<(E + 255) / 256, 256>>>(ei1, ei1 + E, E, 0);
    k_scatter<<<(E + 255) / 256, 256>>>(ei2, ei2 + E, E, N);

    for (int l = 0; l < 3; l++) {
        k_gemm<<<(NT + 15) / 16, 128>>>(W + l * DIM * DIM,
                                        att_s + l * HEADS * FH,
                                        att_d + l * HEADS * FH, NT);
        k_attn<<<(NT * 32 + 255) / 256, 256>>>(bias + l * DIM, NT);
    }

    k_zero_gate<<<1, 256>>>();
    k_gate<<<(NT + 7) / 8, 256>>>(gw, gb, N);
    k_gsum<<<1024, 128>>>(N);
    k_final<<<1, 128>>>(fc1w, fc1b, fc2w, fc2b, (float*)d_out);
}

// round 3
// speedup vs baseline: 1.6334x; 1.3107x over previous
#include <cuda_runtime.h>
#include <cuda_bf16.h>

#define NMAX 50000
#define EMAX 600000
#define NT2 (2 * NMAX)
#define ET2 (2 * EMAX)
#define DIM 128
#define HEADS 4
#define FH 32
#define NEG_SLOPE 0.2f

// ---------------- scratch (static device globals; no allocs) ----------------
__device__ float d_x[NT2 * DIM];
__device__ float d_h[NT2 * DIM];
__device__ float d_asrc[NT2 * HEADS];
__device__ float d_adst[NT2 * HEADS];
__device__ float d_alpha[ET2 * HEADS];
__device__ float d_gate[NT2];
__device__ float d_gvec[2 * DIM];
__device__ float d_gsum[2];
__device__ float d_gmax[12];            // per-layer (3) per-head (4) global max of alpha_src
__device__ int d_deg[NT2];
__device__ int d_off[NT2 + 1];
__device__ int d_cur[NT2];
__device__ int d_csrc[ET2];
__device__ int d_bsum[128];
__device__ int d_boff[128];

__device__ __forceinline__ float leaky(float x) { return x > 0.f ? x : NEG_SLOPE * x; }

__device__ __forceinline__ unsigned f2tf32(float x) {
    unsigned r;
    asm("cvt.rna.tf32.f32 %0, %1;" : "=r"(r) : "f"(x));
    return r;
}

__device__ __forceinline__ void mma_tf32(float* d, const unsigned* a, unsigned b0, unsigned b1) {
    asm volatile("mma.sync.aligned.m16n8k8.row.col.f32.tf32.tf32.f32 "
                 "{%0,%1,%2,%3}, {%4,%5,%6,%7}, {%8,%9}, {%0,%1,%2,%3};\n"
                 : "+f"(d[0]), "+f"(d[1]), "+f"(d[2]), "+f"(d[3])
                 : "r"(a[0]), "r"(a[1]), "r"(a[2]), "r"(a[3]), "r"(b0), "r"(b1));
}

__device__ __forceinline__ void atomicMaxF(float* addr, float v) {
    int old = __float_as_int(*addr);
    while (__int_as_float(old) < v) {
        int assumed = old;
        old = atomicCAS((int*)addr, assumed, __float_as_int(v));
        if (old == assumed) break;
    }
}

// ---------------- embed gather (both graphs) ----------------
__global__ void k_gather(const int* __restrict__ x1, const int* __restrict__ x2,
                         const float* __restrict__ embed, int n) {
    int t = blockIdx.x * blockDim.x + threadIdx.x;
    if (t >= 2 * n * 32) return;
    int node = t >> 5, j = t & 31;
    int id = (node < n) ? x1[node] : x2[node - n];
    ((float4*)(d_x + (size_t)node * DIM))[j] = ((const float4*)(embed + (size_t)id * DIM))[j];
}

// ---------------- CSR build ----------------
__global__ void k_zero_deg(int nt) {
    int i = blockIdx.x * blockDim.x + threadIdx.x;
    if (i < nt) d_deg[i] = 0;
    if (i < 12) d_gmax[i] = -1e30f;
}

__global__ void k_hist(const int* __restrict__ dst, int E, int off) {
    int i = blockIdx.x * blockDim.x + threadIdx.x;
    if (i < E) atomicAdd(&d_deg[dst[i] + off], 1);
}

__global__ void k_blocksum(int nt) {
    __shared__ int ws[8];
    int base = blockIdx.x * 2048 + threadIdx.x * 8;
    int s = 0;
    #pragma unroll
    for (int k = 0; k < 8; k++) {
        int i = base + k;
        if (i < nt) s += d_deg[i];
    }
    #pragma unroll
    for (int d = 16; d; d >>= 1) s += __shfl_down_sync(0xFFFFFFFFu, s, d);
    if ((threadIdx.x & 31) == 0) ws[threadIdx.x >> 5] = s;
    __syncthreads();
    if (threadIdx.x == 0) {
        int t = 0;
        #pragma unroll
        for (int w = 0; w < 8; w++) t += ws[w];
        d_bsum[blockIdx.x] = t;
    }
}

__global__ void k_scanb(int nb) {
    __shared__ int ws[4];
    int tid = threadIdx.x, lane = tid & 31, wid = tid >> 5;
    int v = (tid < nb) ? d_bsum[tid] : 0;
    int x = v;
    #pragma unroll
    for (int d = 1; d < 32; d <<= 1) {
        int y = __shfl_up_sync(0xFFFFFFFFu, x, d);
        if (lane >= d) x += y;
    }
    if (lane == 31) ws[wid] = x;
    __syncthreads();
    int add = 0;
    for (int w = 0; w < wid; w++) add += ws[w];
    if (tid < nb) d_boff[tid] = add + x - v;
}

__global__ void k_scanlocal(int nt) {
    __shared__ int wtot[8];
    __shared__ int wexc[8];
    int tid = threadIdx.x, lane = tid & 31, wid = tid >> 5;
    int base = blockIdx.x * 2048 + tid * 8;
    int vals[8];
    int tsum = 0;
    #pragma unroll
    for (int k = 0; k < 8; k++) {
        int i = base + k;
        vals[k] = (i < nt) ? d_deg[i] : 0;
        tsum += vals[k];
    }
    int x = tsum;
    #pragma unroll
    for (int d = 1; d < 32; d <<= 1) {
        int y = __shfl_up_sync(0xFFFFFFFFu, x, d);
        if (lane >= d) x += y;
    }
    if (lane == 31) wtot[wid] = x;
    __syncthreads();
    if (tid == 0) {
        int acc = 0;
        #pragma unroll
        for (int w = 0; w < 8; w++) { wexc[w] = acc; acc += wtot[w]; }
    }
    __syncthreads();
    int running = d_boff[blockIdx.x] + wexc[wid] + (x - tsum);
    #pragma unroll
    for (int k = 0; k < 8; k++) {
        int i = base + k;
        if (i < nt) {
            d_off[i] = running;
            d_cur[i] = running;
            running += vals[k];
            if (i == nt - 1) d_off[nt] = running;
        }
    }
}

__global__ void k_scatter(const int* __restrict__ src, const int* __restrict__ dst,
                          int E, int off) {
    int i = blockIdx.x * blockDim.x + threadIdx.x;
    if (i < E) {
        int p = atomicAdd(&d_cur[dst[i] + off], 1);
        d_csrc[p] = src[i] + off;
    }
}

// ---------------- GEMM: h = x @ W via 3xTF32 tensor cores ----------------
// Block: 128 threads (4 warps). Tile: 64 rows x 128 cols.
// warp: wm = warp&1 selects 32-row half; wn = warp>>1 selects 64-col half.
__global__ __launch_bounds__(128) void k_gemm(const float* __restrict__ W,
                                              const float* __restrict__ att_s,
                                              const float* __restrict__ att_d,
                                              int layer, int nt) {
    __shared__ float xs[64][132];   // padded: 132 % 32 == 4 -> conflict-free quads
    int tid = threadIdx.x, warp = tid >> 5, lane = tid & 31;
    int lr = lane >> 2, lq = lane & 3;
    int n0 = blockIdx.x * 64;

    for (int t = tid; t < 2048; t += 128) {
        int r = t >> 5, c4 = t & 31;
        float4 v = (n0 + r < nt) ? ((const float4*)(d_x + (size_t)(n0 + r) * DIM))[c4]
                                 : make_float4(0.f, 0.f, 0.f, 0.f);
        *(float4*)&xs[r][c4 * 4] = v;
    }
    __syncthreads();

    int wm = warp & 1, wn = warp >> 1;
    float acc[2][8][4];
    #pragma unroll
    for (int a = 0; a < 2; a++)
        #pragma unroll
        for (int b = 0; b < 8; b++)
            #pragma unroll
            for (int c = 0; c < 4; c++) acc[a][b][c] = 0.f;

    #pragma unroll 2
    for (int k = 0; k < 16; k++) {
        int kb = k * 8;
        unsigned ahi[2][4], alo[2][4];
        #pragma unroll
        for (int mt = 0; mt < 2; mt++) {
            int rb = wm * 32 + mt * 16;
            float av[4];
            av[0] = xs[rb + lr][kb + lq];
            av[1] = xs[rb + lr + 8][kb + lq];
            av[2] = xs[rb + lr][kb + lq + 4];
            av[3] = xs[rb + lr + 8][kb + lq + 4];
            #pragma unroll
            for (int i = 0; i < 4; i++) {
                ahi[mt][i] = f2tf32(av[i]);
                alo[mt][i] = f2tf32(av[i] - __uint_as_float(ahi[mt][i]));
            }
        }
        #pragma unroll
        for (int n8 = 0; n8 < 8; n8++) {
            int nb = wn * 64 + n8 * 8;
            float w0 = __ldg(&W[(kb + lq) * DIM + nb + lr]);
            float w1 = __ldg(&W[(kb + lq + 4) * DIM + nb + lr]);
            unsigned bh0 = f2tf32(w0), bh1 = f2tf32(w1);
            unsigned bl0 = f2tf32(w0 - __uint_as_float(bh0));
            unsigned bl1 = f2tf32(w1 - __uint_as_float(bh1));
            #pragma unroll
            for (int mt = 0; mt < 2; mt++) {
                mma_tf32(acc[mt][n8], ahi[mt], bh0, bh1);
                mma_tf32(acc[mt][n8], alo[mt], bh0, bh1);
                mma_tf32(acc[mt][n8], ahi[mt], bl0, bl1);
            }
        }
    }

    // epilogue: store h, per-head alpha dots, global alpha_src max
    float hs[4][2], hd[4][2];
    #pragma unroll
    for (int i = 0; i < 4; i++) { hs[i][0] = hs[i][1] = hd[i][0] = hd[i][1] = 0.f; }

    #pragma unroll
    for (int n8 = 0; n8 < 8; n8++) {
        int nb = wn * 64 + n8 * 8 + 2 * lq;
        float2 s2 = *(const float2*)&att_s[nb];
        float2 dd2 = *(const float2*)&att_d[nb];
        int hl = n8 >> 2;
        #pragma unroll
        for (int mt = 0; mt < 2; mt++) {
            #pragma unroll
            for (int rh = 0; rh < 2; rh++) {
                float c0 = acc[mt][n8][rh * 2], c1 = acc[mt][n8][rh * 2 + 1];
                int node = n0 + wm * 32 + mt * 16 + rh * 8 + lr;
                if (node < nt)
                    *(float2*)&d_h[(size_t)node * DIM + nb] = make_float2(c0, c1);
                int ri = mt * 2 + rh;
                hs[ri][hl] += c0 * s2.x + c1 * s2.y;
                hd[ri][hl] += c0 * dd2.x + c1 * dd2.y;
            }
        }
    }

    float wmax[2] = {-1e30f, -1e30f};
    #pragma unroll
    for (int ri = 0; ri < 4; ri++) {
        #pragma unroll
        for (int hl = 0; hl < 2; hl++) {
            float vs = hs[ri][hl], vd = hd[ri][hl];
            vs += __shfl_xor_sync(0xFFFFFFFFu, vs, 1);
            vs += __shfl_xor_sync(0xFFFFFFFFu, vs, 2);
            vd += __shfl_xor_sync(0xFFFFFFFFu, vd, 1);
            vd += __shfl_xor_sync(0xFFFFFFFFu, vd, 2);
            int mt = ri >> 1, rh = ri & 1;
            int node = n0 + wm * 32 + mt * 16 + rh * 8 + lr;
            if (lq == 0 && node < nt) {
                d_asrc[node * HEADS + wn * 2 + hl] = vs;
                d_adst[node * HEADS + wn * 2 + hl] = vd;
            }
            wmax[hl] = fmaxf(wmax[hl], vs);   // 0-padded rows contribute 0: still an upper bound
        }
    }
    #pragma unroll
    for (int hl = 0; hl < 2; hl++) {
        float v = wmax[hl];
        #pragma unroll
        for (int d = 16; d; d >>= 1) v = fmaxf(v, __shfl_xor_sync(0xFFFFFFFFu, v, d));
        if (lane == 0) atomicMaxF(&d_gmax[layer * 4 + wn * 2 + hl], v);
    }
}

// ---------------- fused attention + bias + relu (warp/node, 2 passes) -------
__global__ void k_attn(const float* __restrict__ bias, int layer, int nt) {
    int warp = (blockIdx.x * blockDim.x + threadIdx.x) >> 5;
    int lane = threadIdx.x & 31;
    if (warp >= nt) return;
    int nidx = warp;
    int beg = d_off[nidx], end = d_off[nidx + 1];

    float4 ad4 = ((const float4*)d_adst)[nidx];
    float ad[4] = {ad4.x, ad4.y, ad4.z, ad4.w};
    float m[4];
    #pragma unroll
    for (int h = 0; h < 4; h++) m[h] = leaky(d_gmax[layer * 4 + h] + ad[h]);

    float4 as4 = ((const float4*)d_asrc)[nidx];
    float exself[4];
    exself[0] = __expf(leaky(as4.x + ad[0]) - m[0]);
    exself[1] = __expf(leaky(as4.y + ad[1]) - m[1]);
    exself[2] = __expf(leaky(as4.z + ad[2]) - m[2]);
    exself[3] = __expf(leaky(as4.w + ad[3]) - m[3]);

    // pass A: exp + sum (m is a global upper bound; softmax is shift-invariant)
    float sum[4] = {0.f, 0.f, 0.f, 0.f};
    for (int p = beg + lane; p < end; p += 32) {
        int s = d_csrc[p];
        float4 a = ((const float4*)d_asrc)[s];
        float e0 = __expf(leaky(a.x + ad[0]) - m[0]);
        float e1 = __expf(leaky(a.y + ad[1]) - m[1]);
        float e2 = __expf(leaky(a.z + ad[2]) - m[2]);
        float e3 = __expf(leaky(a.w + ad[3]) - m[3]);
        ((float4*)d_alpha)[p] = make_float4(e0, e1, e2, e3);
        sum[0] += e0; sum[1] += e1; sum[2] += e2; sum[3] += e3;
    }
    #pragma unroll
    for (int d = 16; d; d >>= 1) {
        #pragma unroll
        for (int h = 0; h < 4; h++)
            sum[h] += __shfl_xor_sync(0xFFFFFFFFu, sum[h], d);
    }

    float inv[4];
    #pragma unroll
    for (int h = 0; h < 4; h++) inv[h] = 1.f / (sum[h] + exself[h]);

    // pass B: feature-parallel aggregation + bias + relu
    int h3 = lane >> 3;
    float a_self = exself[h3] * inv[h3];
    float4 hv = ((const float4*)(d_h + (size_t)nidx * DIM))[lane];
    float4 acc;
    acc.x = a_self * hv.x; acc.y = a_self * hv.y;
    acc.z = a_self * hv.z; acc.w = a_self * hv.w;
    for (int p = beg; p < end; p++) {
        int s = d_csrc[p];
        float a = d_alpha[p * 4 + h3] * inv[h3];
        float4 v = ((const float4*)(d_h + (size_t)s * DIM))[lane];
        acc.x += a * v.x; acc.y += a * v.y;
        acc.z += a * v.z; acc.w += a * v.w;
    }
    float4 b = ((const float4*)bias)[lane];
    acc.x = fmaxf(acc.x + b.x, 0.f);
    acc.y = fmaxf(acc.y + b.y, 0.f);
    acc.z = fmaxf(acc.z + b.z, 0.f);
    acc.w = fmaxf(acc.w + b.w, 0.f);
    ((float4*)(d_x + (size_t)nidx * DIM))[lane] = acc;
}

// ---------------- global attention pooling ----------------
__global__ void k_zero_gate() {
    int j = threadIdx.x;
    if (j < 2 * DIM) d_gvec[j] = 0.f;
    if (j < 2) d_gsum[j] = 0.f;
}

__global__ void k_gate(const float* __restrict__ gw, const float* __restrict__ gb,
                       int n) {
    __shared__ float part[2];
    int warp = (blockIdx.x * blockDim.x + threadIdx.x) >> 5;
    int lane = threadIdx.x & 31;
    if (threadIdx.x < 2) part[threadIdx.x] = 0.f;
    __syncthreads();
    if (warp < 2 * n) {
        float4 xv = ((const float4*)(d_x + (size_t)warp * DIM))[lane];
        float4 wv = ((const float4*)gw)[lane];
        float t = xv.x * wv.x + xv.y * wv.y + xv.z * wv.z + xv.w * wv.w;
        #pragma unroll
        for (int d = 16; d; d >>= 1) t += __shfl_down_sync(0xFFFFFFFFu, t, d);
        if (lane == 0) {
            float s = 1.f / (1.f + __expf(-(t + gb[0])));
            float eg = __expf(s);
            d_gate[warp] = eg;
            atomicAdd(&part[warp >= n ? 1 : 0], eg);
        }
    }
    __syncthreads();
    if (threadIdx.x < 2 && part[threadIdx.x] != 0.f)
        atomicAdd(&d_gsum[threadIdx.x], part[threadIdx.x]);
}

__global__ void k_gsum(int n) {
    int j = threadIdx.x;
    int g = (blockIdx.x >= 512) ? 1 : 0;
    int b = blockIdx.x & 511;
    float acc = 0.f;
    for (int i = b; i < n; i += 512) {
        int node = g * n + i;
        acc += d_gate[node] * d_x[(size_t)node * DIM + j];
    }
    atomicAdd(&d_gvec[g * DIM + j], acc);
}

// ---------------- final MLP ----------------
__global__ void k_final(const float* __restrict__ fc1_w, const float* __restrict__ fc1_b,
                        const float* __restrict__ fc2_w, const float* __restrict__ fc2_b,
                        float* __restrict__ out) {
    __shared__ float red[4];
    int j = threadIdx.x;
    float inv1 = 1.f / d_gsum[0];
    float inv2 = 1.f / d_gsum[1];
    float acc = fc1_b[j];
    #pragma unroll 4
    for (int k = 0; k < DIM; k++)
        acc += d_gvec[k] * inv1 * fc1_w[k * DIM + j];
    #pragma unroll 4
    for (int k = 0; k < DIM; k++)
        acc += d_gvec[DIM + k] * inv2 * fc1_w[(DIM + k) * DIM + j];
    float v = fmaxf(acc, 0.f) * fc2_w[j];
    #pragma unroll
    for (int d = 16; d; d >>= 1) v += __shfl_down_sync(0xFFFFFFFFu, v, d);
    if ((j & 31) == 0) red[j >> 5] = v;
    __syncthreads();
    if (j == 0) out[0] = red[0] + red[1] + red[2] + red[3] + fc2_b[0];
}

// ---------------- orchestration ----------------
extern "C" void kernel_launch(void* const* d_in, const int* in_sizes, int n_in,
                              void* d_out, int out_size) {
    (void)n_in; (void)out_size;
    const int*   x1    = (const int*)d_in[0];
    const int*   x2    = (const int*)d_in[1];
    const int*   ei1   = (const int*)d_in[2];
    const int*   ei2   = (const int*)d_in[3];
    const float* embed = (const float*)d_in[4];
    const float* W     = (const float*)d_in[5];
    const float* att_s = (const float*)d_in[6];
    const float* att_d = (const float*)d_in[7];
    const float* bias  = (const float*)d_in[8];
    const float* gw    = (const float*)d_in[9];
    const float* gb    = (const float*)d_in[10];
    const float* fc1w  = (const float*)d_in[11];
    const float* fc1b  = (const float*)d_in[12];
    const float* fc2w  = (const float*)d_in[13];
    const float* fc2b  = (const float*)d_in[14];

    int N = in_sizes[0];
    int E = in_sizes[2] / 2;
    int NT = 2 * N;
    int nb = (NT + 2047) / 2048;

    k_gather<<<(NT * 32 + 255) / 256, 256>>>(x1, x2, embed, N);
    k_zero_deg<<<(NT + 255) / 256, 256>>>(NT);
    k_hist<<<(E + 255) / 256, 256>>>(ei1 + E, E, 0);
    k_hist<<<(E + 255) / 256, 256>>>(ei2 + E, E, N);
    k_blocksum<<<nb, 256>>>(NT);
    k_scanb<<<1, 128>>>(nb);
    k_scanlocal<<<nb, 256>>>(NT);
    k_scatter<<<(E + 255) / 256, 256>>>(ei1, ei1 + E, E, 0);
    k_scatter<<<(E + 255) / 256, 256>>>(ei2, ei2 + E, E, N);

    for (int l = 0; l < 3; l++) {
        k_gemm<<<(NT + 63) / 64, 128>>>(W + l * DIM * DIM,
                                        att_s + l * HEADS * FH,
                                        att_d + l * HEADS * FH, l, NT);
        k_attn<<<(NT * 32 + 255) / 256, 256>>>(bias + l * DIM, l, NT);
    }

    k_zero_gate<<<1, 256>>>();
    k_gate<<<(NT + 7) / 8, 256>>>(gw, gb, N);
    k_gsum<<<1024, 128>>>(N);
    k_final<<<1, 128>>>(fc1w, fc1b, fc2w, fc2b, (float*)d_out);
}

// round 4
// speedup vs baseline: 1.7663x; 1.0814x over previous
#include <cuda_runtime.h>
#include <cuda_bf16.h>

#define NMAX 50000
#define EMAX 600000
#define NT2 (2 * NMAX)
#define ET2 (2 * EMAX)
#define DIM 128
#define HEADS 4
#define FH 32
#define NEG_SLOPE 0.2f

// ---------------- scratch (static device globals; no allocs) ----------------
__device__ float d_x[NT2 * DIM];
__device__ __nv_bfloat16 d_hb[NT2 * DIM];   // h = x@W, bf16 for message gather
__device__ float d_asrc[NT2 * HEADS];
__device__ float d_adst[NT2 * HEADS];
__device__ float d_alpha[ET2 * HEADS];
__device__ float d_gvec[2 * DIM];
__device__ float d_gsum[2];
__device__ float d_gmax[12];
__device__ int d_deg[NT2];
__device__ int d_off[NT2 + 1];
__device__ int d_cur[NT2];
__device__ int d_csrc[ET2];
__device__ int d_bsum[128];
__device__ int d_boff[128];

__device__ __forceinline__ float leaky(float x) { return x > 0.f ? x : NEG_SLOPE * x; }

__device__ __forceinline__ unsigned f2tf32(float x) {
    unsigned r;
    asm("cvt.rna.tf32.f32 %0, %1;" : "=r"(r) : "f"(x));
    return r;
}

__device__ __forceinline__ void mma_tf32(float* d, const unsigned* a, unsigned b0, unsigned b1) {
    asm volatile("mma.sync.aligned.m16n8k8.row.col.f32.tf32.tf32.f32 "
                 "{%0,%1,%2,%3}, {%4,%5,%6,%7}, {%8,%9}, {%0,%1,%2,%3};\n"
                 : "+f"(d[0]), "+f"(d[1]), "+f"(d[2]), "+f"(d[3])
                 : "r"(a[0]), "r"(a[1]), "r"(a[2]), "r"(a[3]), "r"(b0), "r"(b1));
}

__device__ __forceinline__ void atomicMaxF(float* addr, float v) {
    int old = __float_as_int(*addr);
    while (__int_as_float(old) < v) {
        int assumed = old;
        old = atomicCAS((int*)addr, assumed, __float_as_int(v));
        if (old == assumed) break;
    }
}

// ---------------- embed gather (both graphs) ----------------
__global__ void k_gather(const int* __restrict__ x1, const int* __restrict__ x2,
                         const float* __restrict__ embed, int n) {
    int t = blockIdx.x * blockDim.x + threadIdx.x;
    if (t >= 2 * n * 32) return;
    int node = t >> 5, j = t & 31;
    int id = (node < n) ? x1[node] : x2[node - n];
    ((float4*)(d_x + (size_t)node * DIM))[j] = ((const float4*)(embed + (size_t)id * DIM))[j];
}

// ---------------- zero scratch ----------------
__global__ void k_zero(int nt) {
    int i = blockIdx.x * blockDim.x + threadIdx.x;
    if (i < nt) d_deg[i] = 0;
    if (i < 12) d_gmax[i] = -1e30f;
    if (i < 2 * DIM) d_gvec[i] = 0.f;
    if (i < 2) d_gsum[i] = 0.f;
}

__global__ void k_hist(const int* __restrict__ dst, int E, int off) {
    int i = blockIdx.x * blockDim.x + threadIdx.x;
    if (i < E) atomicAdd(&d_deg[dst[i] + off], 1);
}

__global__ void k_blocksum(int nt) {
    __shared__ int ws[8];
    int base = blockIdx.x * 2048 + threadIdx.x * 8;
    int s = 0;
    #pragma unroll
    for (int k = 0; k < 8; k++) {
        int i = base + k;
        if (i < nt) s += d_deg[i];
    }
    #pragma unroll
    for (int d = 16; d; d >>= 1) s += __shfl_down_sync(0xFFFFFFFFu, s, d);
    if ((threadIdx.x & 31) == 0) ws[threadIdx.x >> 5] = s;
    __syncthreads();
    if (threadIdx.x == 0) {
        int t = 0;
        #pragma unroll
        for (int w = 0; w < 8; w++) t += ws[w];
        d_bsum[blockIdx.x] = t;
    }
}

__global__ void k_scanb(int nb) {
    __shared__ int ws[4];
    int tid = threadIdx.x, lane = tid & 31, wid = tid >> 5;
    int v = (tid < nb) ? d_bsum[tid] : 0;
    int x = v;
    #pragma unroll
    for (int d = 1; d < 32; d <<= 1) {
        int y = __shfl_up_sync(0xFFFFFFFFu, x, d);
        if (lane >= d) x += y;
    }
    if (lane == 31) ws[wid] = x;
    __syncthreads();
    int add = 0;
    for (int w = 0; w < wid; w++) add += ws[w];
    if (tid < nb) d_boff[tid] = add + x - v;
}

__global__ void k_scanlocal(int nt) {
    __shared__ int wtot[8];
    __shared__ int wexc[8];
    int tid = threadIdx.x, lane = tid & 31, wid = tid >> 5;
    int base = blockIdx.x * 2048 + tid * 8;
    int vals[8];
    int tsum = 0;
    #pragma unroll
    for (int k = 0; k < 8; k++) {
        int i = base + k;
        vals[k] = (i < nt) ? d_deg[i] : 0;
        tsum += vals[k];
    }
    int x = tsum;
    #pragma unroll
    for (int d = 1; d < 32; d <<= 1) {
        int y = __shfl_up_sync(0xFFFFFFFFu, x, d);
        if (lane >= d) x += y;
    }
    if (lane == 31) wtot[wid] = x;
    __syncthreads();
    if (tid == 0) {
        int acc = 0;
        #pragma unroll
        for (int w = 0; w < 8; w++) { wexc[w] = acc; acc += wtot[w]; }
    }
    __syncthreads();
    int running = d_boff[blockIdx.x] + wexc[wid] + (x - tsum);
    #pragma unroll
    for (int k = 0; k < 8; k++) {
        int i = base + k;
        if (i < nt) {
            d_off[i] = running;
            d_cur[i] = running;
            running += vals[k];
            if (i == nt - 1) d_off[nt] = running;
        }
    }
}

__global__ void k_scatter(const int* __restrict__ src, const int* __restrict__ dst,
                          int E, int off) {
    int i = blockIdx.x * blockDim.x + threadIdx.x;
    if (i < E) {
        int p = atomicAdd(&d_cur[dst[i] + off], 1);
        d_csrc[p] = src[i] + off;
    }
}

// ---------------- GEMM: h = x @ W via 3xTF32 tensor cores ----------------
__global__ __launch_bounds__(128) void k_gemm(const float* __restrict__ W,
                                              const float* __restrict__ att_s,
                                              const float* __restrict__ att_d,
                                              int layer, int nt) {
    __shared__ float xs[64][132];
    int tid = threadIdx.x, warp = tid >> 5, lane = tid & 31;
    int lr = lane >> 2, lq = lane & 3;
    int n0 = blockIdx.x * 64;

    for (int t = tid; t < 2048; t += 128) {
        int r = t >> 5, c4 = t & 31;
        float4 v = (n0 + r < nt) ? ((const float4*)(d_x + (size_t)(n0 + r) * DIM))[c4]
                                 : make_float4(0.f, 0.f, 0.f, 0.f);
        *(float4*)&xs[r][c4 * 4] = v;
    }
    __syncthreads();

    int wm = warp & 1, wn = warp >> 1;
    float acc[2][8][4];
    #pragma unroll
    for (int a = 0; a < 2; a++)
        #pragma unroll
        for (int b = 0; b < 8; b++)
            #pragma unroll
            for (int c = 0; c < 4; c++) acc[a][b][c] = 0.f;

    #pragma unroll 2
    for (int k = 0; k < 16; k++) {
        int kb = k * 8;
        unsigned ahi[2][4], alo[2][4];
        #pragma unroll
        for (int mt = 0; mt < 2; mt++) {
            int rb = wm * 32 + mt * 16;
            float av[4];
            av[0] = xs[rb + lr][kb + lq];
            av[1] = xs[rb + lr + 8][kb + lq];
            av[2] = xs[rb + lr][kb + lq + 4];
            av[3] = xs[rb + lr + 8][kb + lq + 4];
            #pragma unroll
            for (int i = 0; i < 4; i++) {
                ahi[mt][i] = f2tf32(av[i]);
                alo[mt][i] = f2tf32(av[i] - __uint_as_float(ahi[mt][i]));
            }
        }
        #pragma unroll
        for (int n8 = 0; n8 < 8; n8++) {
            int nb = wn * 64 + n8 * 8;
            float w0 = __ldg(&W[(kb + lq) * DIM + nb + lr]);
            float w1 = __ldg(&W[(kb + lq + 4) * DIM + nb + lr]);
            unsigned bh0 = f2tf32(w0), bh1 = f2tf32(w1);
            unsigned bl0 = f2tf32(w0 - __uint_as_float(bh0));
            unsigned bl1 = f2tf32(w1 - __uint_as_float(bh1));
            #pragma unroll
            for (int mt = 0; mt < 2; mt++) {
                mma_tf32(acc[mt][n8], ahi[mt], bh0, bh1);
                mma_tf32(acc[mt][n8], alo[mt], bh0, bh1);
                mma_tf32(acc[mt][n8], ahi[mt], bl0, bl1);
            }
        }
    }

    float hs[4][2], hd[4][2];
    #pragma unroll
    for (int i = 0; i < 4; i++) { hs[i][0] = hs[i][1] = hd[i][0] = hd[i][1] = 0.f; }

    #pragma unroll
    for (int n8 = 0; n8 < 8; n8++) {
        int nb = wn * 64 + n8 * 8 + 2 * lq;
        float2 s2 = *(const float2*)&att_s[nb];
        float2 dd2 = *(const float2*)&att_d[nb];
        int hl = n8 >> 2;
        #pragma unroll
        for (int mt = 0; mt < 2; mt++) {
            #pragma unroll
            for (int rh = 0; rh < 2; rh++) {
                float c0 = acc[mt][n8][rh * 2], c1 = acc[mt][n8][rh * 2 + 1];
                int node = n0 + wm * 32 + mt * 16 + rh * 8 + lr;
                if (node < nt)
                    *(__nv_bfloat162*)&d_hb[(size_t)node * DIM + nb] =
                        __floats2bfloat162_rn(c0, c1);
                int ri = mt * 2 + rh;
                hs[ri][hl] += c0 * s2.x + c1 * s2.y;
                hd[ri][hl] += c0 * dd2.x + c1 * dd2.y;
            }
        }
    }

    float wmax[2] = {-1e30f, -1e30f};
    #pragma unroll
    for (int ri = 0; ri < 4; ri++) {
        #pragma unroll
        for (int hl = 0; hl < 2; hl++) {
            float vs = hs[ri][hl], vd = hd[ri][hl];
            vs += __shfl_xor_sync(0xFFFFFFFFu, vs, 1);
            vs += __shfl_xor_sync(0xFFFFFFFFu, vs, 2);
            vd += __shfl_xor_sync(0xFFFFFFFFu, vd, 1);
            vd += __shfl_xor_sync(0xFFFFFFFFu, vd, 2);
            int mt = ri >> 1, rh = ri & 1;
            int node = n0 + wm * 32 + mt * 16 + rh * 8 + lr;
            if (lq == 0 && node < nt) {
                d_asrc[node * HEADS + wn * 2 + hl] = vs;
                d_adst[node * HEADS + wn * 2 + hl] = vd;
            }
            wmax[hl] = fmaxf(wmax[hl], vs);
        }
    }
    #pragma unroll
    for (int hl = 0; hl < 2; hl++) {
        float v = wmax[hl];
        #pragma unroll
        for (int d = 16; d; d >>= 1) v = fmaxf(v, __shfl_xor_sync(0xFFFFFFFFu, v, d));
        if (lane == 0) atomicMaxF(&d_gmax[layer * 4 + wn * 2 + hl], v);
    }
}

// ------ fused attention + bias + relu (+ pooling epilogue on last layer) ----
__global__ __launch_bounds__(256) void k_attn(const float* __restrict__ bias,
                                              int layer, int nt, int n,
                                              const float* __restrict__ gw,
                                              const float* __restrict__ gb,
                                              int last) {
    __shared__ float sgv[2 * DIM];
    __shared__ float sgs[2];
    int tid = threadIdx.x;
    if (last) {
        if (tid < 2 * DIM) sgv[tid] = 0.f;
        if (tid < 2) sgs[tid] = 0.f;
        __syncthreads();
    }
    int warp = (blockIdx.x * 256 + tid) >> 5;
    int lane = tid & 31;
    bool active = warp < nt;
    int nidx = warp;
    float4 acc = make_float4(0.f, 0.f, 0.f, 0.f);
    int h3 = lane >> 3;

    if (active) {
        int beg = d_off[nidx], end = d_off[nidx + 1];

        float4 ad4 = ((const float4*)d_adst)[nidx];
        float ad[4] = {ad4.x, ad4.y, ad4.z, ad4.w};
        float m[4];
        #pragma unroll
        for (int h = 0; h < 4; h++) m[h] = leaky(d_gmax[layer * 4 + h] + ad[h]);

        float4 as4 = ((const float4*)d_asrc)[nidx];
        float exself[4];
        exself[0] = __expf(leaky(as4.x + ad[0]) - m[0]);
        exself[1] = __expf(leaky(as4.y + ad[1]) - m[1]);
        exself[2] = __expf(leaky(as4.z + ad[2]) - m[2]);
        exself[3] = __expf(leaky(as4.w + ad[3]) - m[3]);

        float sum[4] = {0.f, 0.f, 0.f, 0.f};
        for (int p = beg + lane; p < end; p += 32) {
            int s = d_csrc[p];
            float4 a = ((const float4*)d_asrc)[s];
            float e0 = __expf(leaky(a.x + ad[0]) - m[0]);
            float e1 = __expf(leaky(a.y + ad[1]) - m[1]);
            float e2 = __expf(leaky(a.z + ad[2]) - m[2]);
            float e3 = __expf(leaky(a.w + ad[3]) - m[3]);
            ((float4*)d_alpha)[p] = make_float4(e0, e1, e2, e3);
            sum[0] += e0; sum[1] += e1; sum[2] += e2; sum[3] += e3;
        }
        #pragma unroll
        for (int d = 16; d; d >>= 1) {
            #pragma unroll
            for (int h = 0; h < 4; h++)
                sum[h] += __shfl_xor_sync(0xFFFFFFFFu, sum[h], d);
        }

        float inv[4];
        #pragma unroll
        for (int h = 0; h < 4; h++) inv[h] = 1.f / (sum[h] + exself[h]);

        // pass B: feature-parallel aggregation over bf16 messages
        float a_self = exself[h3] * inv[h3];
        {
            uint2 raw = ((const uint2*)(d_hb + (size_t)nidx * DIM))[lane];
            float2 f0 = __bfloat1622float2(*(__nv_bfloat162*)&raw.x);
            float2 f1 = __bfloat1622float2(*(__nv_bfloat162*)&raw.y);
            acc.x = a_self * f0.x; acc.y = a_self * f0.y;
            acc.z = a_self * f1.x; acc.w = a_self * f1.y;
        }
        for (int p = beg; p < end; p++) {
            int s = d_csrc[p];
            float a = d_alpha[p * 4 + h3] * inv[h3];
            uint2 raw = ((const uint2*)(d_hb + (size_t)s * DIM))[lane];
            float2 f0 = __bfloat1622float2(*(__nv_bfloat162*)&raw.x);
            float2 f1 = __bfloat1622float2(*(__nv_bfloat162*)&raw.y);
            acc.x += a * f0.x; acc.y += a * f0.y;
            acc.z += a * f1.x; acc.w += a * f1.y;
        }
        float4 b = ((const float4*)bias)[lane];
        acc.x = fmaxf(acc.x + b.x, 0.f);
        acc.y = fmaxf(acc.y + b.y, 0.f);
        acc.z = fmaxf(acc.z + b.z, 0.f);
        acc.w = fmaxf(acc.w + b.w, 0.f);
    }

    if (!last) {
        if (active)
            ((float4*)(d_x + (size_t)nidx * DIM))[lane] = acc;
        return;
    }

    // last layer: fused global-attention pooling
    if (active) {
        float4 wv = ((const float4*)gw)[lane];
        float t = acc.x * wv.x + acc.y * wv.y + acc.z * wv.z + acc.w * wv.w;
        #pragma unroll
        for (int d = 16; d; d >>= 1) t += __shfl_xor_sync(0xFFFFFFFFu, t, d);
        float sg = 1.f / (1.f + __expf(-(t + gb[0])));
        float gate = __expf(sg);
        int g = (nidx >= n) ? 1 : 0;
        float* base = sgv + g * DIM + lane * 4;
        atomicAdd(base + 0, gate * acc.x);
        atomicAdd(base + 1, gate * acc.y);
        atomicAdd(base + 2, gate * acc.z);
        atomicAdd(base + 3, gate * acc.w);
        if (lane == 0) atomicAdd(&sgs[g], gate);
    }
    __syncthreads();
    if (tid < 2 && sgs[tid] != 0.f) atomicAdd(&d_gsum[tid], sgs[tid]);
    for (int t = tid; t < 2 * DIM; t += 256) {
        float v = sgv[t];
        if (v != 0.f) atomicAdd(&d_gvec[t], v);
    }
}

// ---------------- final MLP ----------------
__global__ void k_final(const float* __restrict__ fc1_w, const float* __restrict__ fc1_b,
                        const float* __restrict__ fc2_w, const float* __restrict__ fc2_b,
                        float* __restrict__ out) {
    __shared__ float red[4];
    int j = threadIdx.x;
    float inv1 = 1.f / d_gsum[0];
    float inv2 = 1.f / d_gsum[1];
    float acc = fc1_b[j];
    #pragma unroll 4
    for (int k = 0; k < DIM; k++)
        acc += d_gvec[k] * inv1 * fc1_w[k * DIM + j];
    #pragma unroll 4
    for (int k = 0; k < DIM; k++)
        acc += d_gvec[DIM + k] * inv2 * fc1_w[(DIM + k) * DIM + j];
    float v = fmaxf(acc, 0.f) * fc2_w[j];
    #pragma unroll
    for (int d = 16; d; d >>= 1) v += __shfl_down_sync(0xFFFFFFFFu, v, d);
    if ((j & 31) == 0) red[j >> 5] = v;
    __syncthreads();
    if (j == 0) out[0] = red[0] + red[1] + red[2] + red[3] + fc2_b[0];
}

// ---------------- orchestration ----------------
extern "C" void kernel_launch(void* const* d_in, const int* in_sizes, int n_in,
                              void* d_out, int out_size) {
    (void)n_in; (void)out_size;
    const int*   x1    = (const int*)d_in[0];
    const int*   x2    = (const int*)d_in[1];
    const int*   ei1   = (const int*)d_in[2];
    const int*   ei2   = (const int*)d_in[3];
    const float* embed = (const float*)d_in[4];
    const float* W     = (const float*)d_in[5];
    const float* att_s = (const float*)d_in[6];
    const float* att_d = (const float*)d_in[7];
    const float* bias  = (const float*)d_in[8];
    const float* gw    = (const float*)d_in[9];
    const float* gb    = (const float*)d_in[10];
    const float* fc1w  = (const float*)d_in[11];
    const float* fc1b  = (const float*)d_in[12];
    const float* fc2w  = (const float*)d_in[13];
    const float* fc2b  = (const float*)d_in[14];

    int N = in_sizes[0];
    int E = in_sizes[2] / 2;
    int NT = 2 * N;
    int nb = (NT + 2047) / 2048;

    k_gather<<<(NT * 32 + 255) / 256, 256>>>(x1, x2, embed, N);
    k_zero<<<(NT + 255) / 256, 256>>>(NT);
    k_hist<<<(E + 255) / 256, 256>>>(ei1 + E, E, 0);
    k_hist<<<(E + 255) / 256, 256>>>(ei2 + E, E, N);
    k_blocksum<<<nb, 256>>>(NT);
    k_scanb<<<1, 128>>>(nb);
    k_scanlocal<<<nb, 256>>>(NT);
    k_scatter<<<(E + 255) / 256, 256>>>(ei1, ei1 + E, E, 0);
    k_scatter<<<(E + 255) / 256, 256>>>(ei2, ei2 + E, E, N);

    for (int l = 0; l < 3; l++) {
        k_gemm<<<(NT + 63) / 64, 128>>>(W + l * DIM * DIM,
                                        att_s + l * HEADS * FH,
                                        att_d + l * HEADS * FH, l, NT);
        k_attn<<<(NT * 32 + 255) / 256, 256>>>(bias + l * DIM, l, NT, N,
                                               gw, gb, (l == 2) ? 1 : 0);
    }

    k_final<<<1, 128>>>(fc1w, fc1b, fc2w, fc2b, (float*)d_out);
}

// round 5
// speedup vs baseline: 1.9255x; 1.0902x over previous
#include <cuda_runtime.h>
#include <cuda_bf16.h>

#define NMAX 50000
#define EMAX 600000
#define NT2 (2 * NMAX)
#define ET2 (2 * EMAX)
#define DIM 128
#define HEADS 4
#define FH 32
#define NEG_SLOPE 0.2f

// ---------------- scratch (static device globals; no allocs) ----------------
__device__ float d_x[NT2 * DIM];            // features between layers (1,2 input)
__device__ __nv_bfloat16 d_hb[NT2 * DIM];   // h = x@W (bf16 messages)
__device__ float d_asrc[NT2 * HEADS];
__device__ float d_adst[NT2 * HEADS];
__device__ float d_gvec[2 * DIM];
__device__ float d_gsum[2];
__device__ float d_gmax[12];
__device__ unsigned d_whi[3 * DIM * DIM];
__device__ unsigned d_wlo[3 * DIM * DIM];
__device__ int d_deg[NT2];
__device__ int d_off[NT2 + 1];
__device__ int d_cur[NT2];
__device__ int d_csrc[ET2];
__device__ int d_bsum[128];
__device__ int d_boff[128];

__device__ __forceinline__ float leaky(float x) { return x > 0.f ? x : NEG_SLOPE * x; }

__device__ __forceinline__ unsigned f2tf32(float x) {
    unsigned r;
    asm("cvt.rna.tf32.f32 %0, %1;" : "=r"(r) : "f"(x));
    return r;
}

__device__ __forceinline__ void mma_tf32(float* d, const unsigned* a, unsigned b0, unsigned b1) {
    asm volatile("mma.sync.aligned.m16n8k8.row.col.f32.tf32.tf32.f32 "
                 "{%0,%1,%2,%3}, {%4,%5,%6,%7}, {%8,%9}, {%0,%1,%2,%3};\n"
                 : "+f"(d[0]), "+f"(d[1]), "+f"(d[2]), "+f"(d[3])
                 : "r"(a[0]), "r"(a[1]), "r"(a[2]), "r"(a[3]), "r"(b0), "r"(b1));
}

__device__ __forceinline__ void atomicMaxF(float* addr, float v) {
    int old = __float_as_int(*addr);
    while (__int_as_float(old) < v) {
        int assumed = old;
        old = atomicCAS((int*)addr, assumed, __float_as_int(v));
        if (old == assumed) break;
    }
}

// ---------------- zero scratch ----------------
__global__ void k_zero(int nt) {
    int i = blockIdx.x * blockDim.x + threadIdx.x;
    if (i < nt) d_deg[i] = 0;
    if (i < 12) d_gmax[i] = -1e30f;
    if (i < 2 * DIM) d_gvec[i] = 0.f;
    if (i < 2) d_gsum[i] = 0.f;
}

// ---------------- W pre-split into tf32 hi/lo ----------------
__global__ void k_wprep(const float* __restrict__ W) {
    int i = blockIdx.x * blockDim.x + threadIdx.x;
    if (i < 3 * DIM * DIM) {
        float w = W[i];
        unsigned hi = f2tf32(w);
        d_whi[i] = hi;
        d_wlo[i] = f2tf32(w - __uint_as_float(hi));
    }
}

// ---------------- CSR build (both graphs in one launch) ----------------
__global__ void k_hist2(const int* __restrict__ ei1, const int* __restrict__ ei2,
                        int E, int n) {
    int i = blockIdx.x * blockDim.x + threadIdx.x;
    if (i < E) atomicAdd(&d_deg[ei1[E + i]], 1);
    else if (i < 2 * E) atomicAdd(&d_deg[ei2[i] + n], 1);   // ei2[E + (i-E)]
}

__global__ void k_blocksum(int nt) {
    __shared__ int ws[8];
    int base = blockIdx.x * 2048 + threadIdx.x * 8;
    int s = 0;
    #pragma unroll
    for (int k = 0; k < 8; k++) {
        int i = base + k;
        if (i < nt) s += d_deg[i];
    }
    #pragma unroll
    for (int d = 16; d; d >>= 1) s += __shfl_down_sync(0xFFFFFFFFu, s, d);
    if ((threadIdx.x & 31) == 0) ws[threadIdx.x >> 5] = s;
    __syncthreads();
    if (threadIdx.x == 0) {
        int t = 0;
        #pragma unroll
        for (int w = 0; w < 8; w++) t += ws[w];
        d_bsum[blockIdx.x] = t;
    }
}

__global__ void k_scanb(int nb) {
    __shared__ int ws[4];
    int tid = threadIdx.x, lane = tid & 31, wid = tid >> 5;
    int v = (tid < nb) ? d_bsum[tid] : 0;
    int x = v;
    #pragma unroll
    for (int d = 1; d < 32; d <<= 1) {
        int y = __shfl_up_sync(0xFFFFFFFFu, x, d);
        if (lane >= d) x += y;
    }
    if (lane == 31) ws[wid] = x;
    __syncthreads();
    int add = 0;
    for (int w = 0; w < wid; w++) add += ws[w];
    if (tid < nb) d_boff[tid] = add + x - v;
}

__global__ void k_scanlocal(int nt) {
    __shared__ int wtot[8];
    __shared__ int wexc[8];
    int tid = threadIdx.x, lane = tid & 31, wid = tid >> 5;
    int base = blockIdx.x * 2048 + tid * 8;
    int vals[8];
    int tsum = 0;
    #pragma unroll
    for (int k = 0; k < 8; k++) {
        int i = base + k;
        vals[k] = (i < nt) ? d_deg[i] : 0;
        tsum += vals[k];
    }
    int x = tsum;
    #pragma unroll
    for (int d = 1; d < 32; d <<= 1) {
        int y = __shfl_up_sync(0xFFFFFFFFu, x, d);
        if (lane >= d) x += y;
    }
    if (lane == 31) wtot[wid] = x;
    __syncthreads();
    if (tid == 0) {
        int acc = 0;
        #pragma unroll
        for (int w = 0; w < 8; w++) { wexc[w] = acc; acc += wtot[w]; }
    }
    __syncthreads();
    int running = d_boff[blockIdx.x] + wexc[wid] + (x - tsum);
    #pragma unroll
    for (int k = 0; k < 8; k++) {
        int i = base + k;
        if (i < nt) {
            d_off[i] = running;
            d_cur[i] = running;
            running += vals[k];
            if (i == nt - 1) d_off[nt] = running;
        }
    }
}

__global__ void k_scatter2(const int* __restrict__ ei1, const int* __restrict__ ei2,
                           int E, int n) {
    int i = blockIdx.x * blockDim.x + threadIdx.x;
    if (i < E) {
        int p = atomicAdd(&d_cur[ei1[E + i]], 1);
        d_csrc[p] = ei1[i];
    } else if (i < 2 * E) {
        int j = i - E;
        int p = atomicAdd(&d_cur[ei2[E + j] + n], 1);
        d_csrc[p] = ei2[j] + n;
    }
}

// ---------------- GEMM: h = x @ W via 3xTF32 tensor cores ----------------
// layer 0 reads embed[ids[row]] directly (no d_x materialization).
__global__ __launch_bounds__(128) void k_gemm(const float* __restrict__ att_s,
                                              const float* __restrict__ att_d,
                                              int layer, int nt, int n,
                                              const int* __restrict__ x1,
                                              const int* __restrict__ x2,
                                              const float* __restrict__ embed) {
    __shared__ float xs[64][132];
    int tid = threadIdx.x, warp = tid >> 5, lane = tid & 31;
    int lr = lane >> 2, lq = lane & 3;
    int n0 = blockIdx.x * 64;

    for (int t = tid; t < 2048; t += 128) {
        int r = t >> 5, c4 = t & 31;
        int node = n0 + r;
        float4 v = make_float4(0.f, 0.f, 0.f, 0.f);
        if (node < nt) {
            const float* row;
            if (layer == 0) {
                int id = (node < n) ? x1[node] : x2[node - n];
                row = embed + (size_t)id * DIM;
            } else {
                row = d_x + (size_t)node * DIM;
            }
            v = ((const float4*)row)[c4];
        }
        *(float4*)&xs[r][c4 * 4] = v;
    }
    __syncthreads();

    int wm = warp & 1, wn = warp >> 1;
    const unsigned* whi = d_whi + layer * DIM * DIM;
    const unsigned* wlo = d_wlo + layer * DIM * DIM;
    float acc[2][8][4];
    #pragma unroll
    for (int a = 0; a < 2; a++)
        #pragma unroll
        for (int b = 0; b < 8; b++)
            #pragma unroll
            for (int c = 0; c < 4; c++) acc[a][b][c] = 0.f;

    #pragma unroll 2
    for (int k = 0; k < 16; k++) {
        int kb = k * 8;
        unsigned ahi[2][4], alo[2][4];
        #pragma unroll
        for (int mt = 0; mt < 2; mt++) {
            int rb = wm * 32 + mt * 16;
            float av[4];
            av[0] = xs[rb + lr][kb + lq];
            av[1] = xs[rb + lr + 8][kb + lq];
            av[2] = xs[rb + lr][kb + lq + 4];
            av[3] = xs[rb + lr + 8][kb + lq + 4];
            #pragma unroll
            for (int i = 0; i < 4; i++) {
                ahi[mt][i] = f2tf32(av[i]);
                alo[mt][i] = f2tf32(av[i] - __uint_as_float(ahi[mt][i]));
            }
        }
        #pragma unroll
        for (int n8 = 0; n8 < 8; n8++) {
            int nb = wn * 64 + n8 * 8;
            int i0 = (kb + lq) * DIM + nb + lr;
            int i1 = (kb + lq + 4) * DIM + nb + lr;
            unsigned bh0 = __ldg(&whi[i0]);
            unsigned bh1 = __ldg(&whi[i1]);
            unsigned bl0 = __ldg(&wlo[i0]);
            unsigned bl1 = __ldg(&wlo[i1]);
            #pragma unroll
            for (int mt = 0; mt < 2; mt++) {
                mma_tf32(acc[mt][n8], ahi[mt], bh0, bh1);
                mma_tf32(acc[mt][n8], alo[mt], bh0, bh1);
                mma_tf32(acc[mt][n8], ahi[mt], bl0, bl1);
            }
        }
    }

    float hs[4][2], hd[4][2];
    #pragma unroll
    for (int i = 0; i < 4; i++) { hs[i][0] = hs[i][1] = hd[i][0] = hd[i][1] = 0.f; }

    #pragma unroll
    for (int n8 = 0; n8 < 8; n8++) {
        int nb = wn * 64 + n8 * 8 + 2 * lq;
        float2 s2 = *(const float2*)&att_s[nb];
        float2 dd2 = *(const float2*)&att_d[nb];
        int hl = n8 >> 2;
        #pragma unroll
        for (int mt = 0; mt < 2; mt++) {
            #pragma unroll
            for (int rh = 0; rh < 2; rh++) {
                float c0 = acc[mt][n8][rh * 2], c1 = acc[mt][n8][rh * 2 + 1];
                int node = n0 + wm * 32 + mt * 16 + rh * 8 + lr;
                if (node < nt)
                    *(__nv_bfloat162*)&d_hb[(size_t)node * DIM + nb] =
                        __floats2bfloat162_rn(c0, c1);
                int ri = mt * 2 + rh;
                hs[ri][hl] += c0 * s2.x + c1 * s2.y;
                hd[ri][hl] += c0 * dd2.x + c1 * dd2.y;
            }
        }
    }

    float wmax[2] = {-1e30f, -1e30f};
    #pragma unroll
    for (int ri = 0; ri < 4; ri++) {
        #pragma unroll
        for (int hl = 0; hl < 2; hl++) {
            float vs = hs[ri][hl], vd = hd[ri][hl];
            vs += __shfl_xor_sync(0xFFFFFFFFu, vs, 1);
            vs += __shfl_xor_sync(0xFFFFFFFFu, vs, 2);
            vd += __shfl_xor_sync(0xFFFFFFFFu, vd, 1);
            vd += __shfl_xor_sync(0xFFFFFFFFu, vd, 2);
            int mt = ri >> 1, rh = ri & 1;
            int node = n0 + wm * 32 + mt * 16 + rh * 8 + lr;
            if (lq == 0 && node < nt) {
                d_asrc[node * HEADS + wn * 2 + hl] = vs;
                d_adst[node * HEADS + wn * 2 + hl] = vd;
            }
            wmax[hl] = fmaxf(wmax[hl], vs);
        }
    }
    #pragma unroll
    for (int hl = 0; hl < 2; hl++) {
        float v = wmax[hl];
        #pragma unroll
        for (int d = 16; d; d >>= 1) v = fmaxf(v, __shfl_xor_sync(0xFFFFFFFFu, v, d));
        if (lane == 0) atomicMaxF(&d_gmax[layer * 4 + wn * 2 + hl], v);
    }
}

// ------ SINGLE-PASS attention + bias + relu (+ pooling on last layer) -------
// Global-bound shift m makes normalization a post-scale: one sweep computes
// both sum(e) and sum(e*h). Every lane sees every edge -> no reductions.
__global__ __launch_bounds__(256) void k_attn(const float* __restrict__ bias,
                                              int layer, int nt, int n,
                                              const float* __restrict__ gw,
                                              const float* __restrict__ gb,
                                              int last) {
    __shared__ float sgv[2 * DIM];
    __shared__ float sgs[2];
    int tid = threadIdx.x;
    if (last) {
        if (tid < 2 * DIM) sgv[tid] = 0.f;
        if (tid < 2) sgs[tid] = 0.f;
        __syncthreads();
    }
    int warp = (blockIdx.x * 256 + tid) >> 5;
    int lane = tid & 31;
    bool active = warp < nt;
    int nidx = warp;
    float4 acc = make_float4(0.f, 0.f, 0.f, 0.f);
    int h3 = lane >> 3;

    if (active) {
        int beg = d_off[nidx], end = d_off[nidx + 1];
        float ad_h = __ldg(&d_adst[nidx * HEADS + h3]);
        float m_h = leaky(__ldg(&d_gmax[layer * 4 + h3]) + ad_h);
        float as_h = __ldg(&d_asrc[nidx * HEADS + h3]);
        float exself = __expf(leaky(as_h + ad_h) - m_h);

        // self-loop contribution
        float sum = exself;
        {
            uint2 raw = ((const uint2*)(d_hb + (size_t)nidx * DIM))[lane];
            float2 f0 = __bfloat1622float2(*(__nv_bfloat162*)&raw.x);
            float2 f1 = __bfloat1622float2(*(__nv_bfloat162*)&raw.y);
            acc.x = exself * f0.x; acc.y = exself * f0.y;
            acc.z = exself * f1.x; acc.w = exself * f1.y;
        }
        for (int p = beg; p < end; p++) {
            int s = d_csrc[p];
            float a = __ldg(&d_asrc[s * HEADS + h3]);
            float e = __expf(leaky(a + ad_h) - m_h);
            sum += e;
            uint2 raw = ((const uint2*)(d_hb + (size_t)s * DIM))[lane];
            float2 f0 = __bfloat1622float2(*(__nv_bfloat162*)&raw.x);
            float2 f1 = __bfloat1622float2(*(__nv_bfloat162*)&raw.y);
            acc.x += e * f0.x; acc.y += e * f0.y;
            acc.z += e * f1.x; acc.w += e * f1.y;
        }
        float inv = 1.f / sum;
        float4 b = ((const float4*)bias)[lane];
        acc.x = fmaxf(acc.x * inv + b.x, 0.f);
        acc.y = fmaxf(acc.y * inv + b.y, 0.f);
        acc.z = fmaxf(acc.z * inv + b.z, 0.f);
        acc.w = fmaxf(acc.w * inv + b.w, 0.f);
    }

    if (!last) {
        if (active)
            ((float4*)(d_x + (size_t)nidx * DIM))[lane] = acc;
        return;
    }

    // last layer: fused global-attention pooling
    if (active) {
        float4 wv = ((const float4*)gw)[lane];
        float t = acc.x * wv.x + acc.y * wv.y + acc.z * wv.z + acc.w * wv.w;
        #pragma unroll
        for (int d = 16; d; d >>= 1) t += __shfl_xor_sync(0xFFFFFFFFu, t, d);
        float sg = 1.f / (1.f + __expf(-(t + gb[0])));
        float gate = __expf(sg);
        int g = (nidx >= n) ? 1 : 0;
        float* base = sgv + g * DIM + lane * 4;
        atomicAdd(base + 0, gate * acc.x);
        atomicAdd(base + 1, gate * acc.y);
        atomicAdd(base + 2, gate * acc.z);
        atomicAdd(base + 3, gate * acc.w);
        if (lane == 0) atomicAdd(&sgs[g], gate);
    }
    __syncthreads();
    if (tid < 2 && sgs[tid] != 0.f) atomicAdd(&d_gsum[tid], sgs[tid]);
    for (int t = tid; t < 2 * DIM; t += 256) {
        float v = sgv[t];
        if (v != 0.f) atomicAdd(&d_gvec[t], v);
    }
}

// ---------------- final MLP ----------------
__global__ void k_final(const float* __restrict__ fc1_w, const float* __restrict__ fc1_b,
                        const float* __restrict__ fc2_w, const float* __restrict__ fc2_b,
                        float* __restrict__ out) {
    __shared__ float red[4];
    int j = threadIdx.x;
    float inv1 = 1.f / d_gsum[0];
    float inv2 = 1.f / d_gsum[1];
    float acc = fc1_b[j];
    #pragma unroll 4
    for (int k = 0; k < DIM; k++)
        acc += d_gvec[k] * inv1 * fc1_w[k * DIM + j];
    #pragma unroll 4
    for (int k = 0; k < DIM; k++)
        acc += d_gvec[DIM + k] * inv2 * fc1_w[(DIM + k) * DIM + j];
    float v = fmaxf(acc, 0.f) * fc2_w[j];
    #pragma unroll
    for (int d = 16; d; d >>= 1) v += __shfl_down_sync(0xFFFFFFFFu, v, d);
    if ((j & 31) == 0) red[j >> 5] = v;
    __syncthreads();
    if (j == 0) out[0] = red[0] + red[1] + red[2] + red[3] + fc2_b[0];
}

// ---------------- orchestration ----------------
extern "C" void kernel_launch(void* const* d_in, const int* in_sizes, int n_in,
                              void* d_out, int out_size) {
    (void)n_in; (void)out_size;
    const int*   x1    = (const int*)d_in[0];
    const int*   x2    = (const int*)d_in[1];
    const int*   ei1   = (const int*)d_in[2];
    const int*   ei2   = (const int*)d_in[3];
    const float* embed = (const float*)d_in[4];
    const float* W     = (const float*)d_in[5];
    const float* att_s = (const float*)d_in[6];
    const float* att_d = (const float*)d_in[7];
    const float* bias  = (const float*)d_in[8];
    const float* gw    = (const float*)d_in[9];
    const float* gb    = (const float*)d_in[10];
    const float* fc1w  = (const float*)d_in[11];
    const float* fc1b  = (const float*)d_in[12];
    const float* fc2w  = (const float*)d_in[13];
    const float* fc2b  = (const float*)d_in[14];

    int N = in_sizes[0];
    int E = in_sizes[2] / 2;
    int NT = 2 * N;
    int nb = (NT + 2047) / 2048;

    k_zero<<<(NT + 255) / 256, 256>>>(NT);
    k_wprep<<<(3 * DIM * DIM + 255) / 256, 256>>>(W);
    k_hist2<<<(2 * E + 255) / 256, 256>>>(ei1, ei2, E, N);
    k_blocksum<<<nb, 256>>>(NT);
    k_scanb<<<1, 128>>>(nb);
    k_scanlocal<<<nb, 256>>>(NT);
    k_scatter2<<<(2 * E + 255) / 256, 256>>>(ei1, ei2, E, N);

    for (int l = 0; l < 3; l++) {
        k_gemm<<<(NT + 63) / 64, 128>>>(att_s + l * HEADS * FH,
                                        att_d + l * HEADS * FH,
                                        l, NT, N, x1, x2, embed);
        k_attn<<<(NT * 32 + 255) / 256, 256>>>(bias + l * DIM, l, NT, N,
                                               gw, gb, (l == 2) ? 1 : 0);
    }

    k_final<<<1, 128>>>(fc1w, fc1b, fc2w, fc2b, (float*)d_out);
}